// round 8
// baseline (speedup 1.0000x reference)
#include <cuda_runtime.h>
#include <cuda_fp16.h>
#include <cstdint>

#define B_     4
#define T_     400
#define U_     64
#define E_     320
#define INNER_ 512
#define VOCAB_ 1024

// ---------------------------------------------------------------------------
// Device-global scratch (no runtime allocation allowed)
// ---------------------------------------------------------------------------
__device__ float  g_encp[B_ * T_ * INNER_];   // enc @ W1[:, :E]
__device__ float  g_decp[B_ * U_ * INNER_];   // dec @ W1[:, E:] + b1
__device__ __half g_w2f[VOCAB_ * INNER_];     // W2 in fp16 (rn)

__device__ __forceinline__ float tanh_approx(float x) {
    float y; asm("tanh.approx.f32 %0, %1;" : "=f"(y) : "f"(x)); return y;
}
__device__ __forceinline__ uint32_t smem_u32(const void* p) {
    uint32_t a;
    asm("{ .reg .u64 t; cvta.to.shared.u64 t, %1; cvt.u32.u64 %0, t; }" : "=r"(a) : "l"(p));
    return a;
}
__device__ __forceinline__ void cp_async16(uint32_t dst, const void* src) {
    asm volatile("cp.async.ca.shared.global [%0], [%1], 16;" :: "r"(dst), "l"(src));
}
__device__ __forceinline__ void cp_commit() {
    asm volatile("cp.async.commit_group;" ::: "memory");
}
__device__ __forceinline__ void cp_wait0() {
    asm volatile("cp.async.wait_group 0;" ::: "memory");
}

// ---------------------------------------------------------------------------
// Kernel 1: projection GEMM (unchanged, passing)
// ---------------------------------------------------------------------------
__global__ __launch_bounds__(256)
void proj_kernel(const float* __restrict__ A, const float* __restrict__ W1,
                 const float* __restrict__ b1, int isDec)
{
    __shared__ float As[16][64];
    __shared__ float Ws[16][68];

    const int tid  = threadIdx.x;
    const int m0   = blockIdx.x * 64;
    const int n0   = blockIdx.y * 64;
    const int koff = isDec ? E_ : 0;

    float acc[4][4] = {};

    for (int k0 = 0; k0 < E_; k0 += 16) {
        #pragma unroll
        for (int i = tid; i < 64 * 16; i += 256) {
            int r = i >> 4, k = i & 15;
            As[k][r] = A[(m0 + r) * E_ + k0 + k];
        }
        #pragma unroll
        for (int i = tid; i < 64 * 16; i += 256) {
            int c = i >> 4, k = i & 15;
            Ws[k][c] = W1[(n0 + c) * (2 * E_) + koff + k0 + k];
        }
        __syncthreads();

        const int ty = tid >> 4, tx = tid & 15;
        #pragma unroll
        for (int k = 0; k < 16; k++) {
            float a[4], w[4];
            #pragma unroll
            for (int i = 0; i < 4; i++) a[i] = As[k][ty * 4 + i];
            #pragma unroll
            for (int j = 0; j < 4; j++) w[j] = Ws[k][tx * 4 + j];
            #pragma unroll
            for (int i = 0; i < 4; i++)
                #pragma unroll
                for (int j = 0; j < 4; j++)
                    acc[i][j] = fmaf(a[i], w[j], acc[i][j]);
        }
        __syncthreads();
    }

    const int ty = tid >> 4, tx = tid & 15;
    float* C = isDec ? g_decp : g_encp;
    #pragma unroll
    for (int i = 0; i < 4; i++)
        #pragma unroll
        for (int j = 0; j < 4; j++) {
            float v = acc[i][j];
            if (isDec) v += b1[n0 + tx * 4 + j];
            C[(m0 + ty * 4 + i) * INNER_ + n0 + tx * 4 + j] = v;
        }
}

// ---------------------------------------------------------------------------
// Kernel 2: W2 fp32 -> fp16 (one-time)
// ---------------------------------------------------------------------------
__global__ __launch_bounds__(256)
void w2half_kernel(const float* __restrict__ W2)
{
    int i = blockIdx.x * 256 + threadIdx.x;
    if (i < VOCAB_ * INNER_) g_w2f[i] = __float2half_rn(W2[i]);
}

// ---------------------------------------------------------------------------
// Kernel 3: fused mma.sync kernel, single-sync double-buffered pipeline.
//   Block tile: 128 rows (16t x 8u) x 256 vocab, K-chunks of 64 (8 chunks).
//   8 warps in 2(m) x 4(n): warp tile 64x64 via m16n8k16 fp16->f32.
//   B (W2 fp16) arrives via cp.async, double-buffered (load c+1 during MMA c).
//   A (h = tanh(enc+dec)) built from DIRECT global reads (L1/L2-hot; the same
//   6KB chunk is shared by 32 CTAs), double-buffered in SMEM.
//   Exactly one __syncthreads per chunk:
//     at sync(c) all warps have finished MMA(c-1), so tanh/cp.async writes to
//     a buffer can never race the MMA two chunks back on that same buffer.
// ---------------------------------------------------------------------------
#define APAD 72

// dynamic smem layout (bytes)
#define O_BIAS  0                               // float[256]          1024
#define O_ASH   1024                            // half[2][128][72]   36864
#define O_BSH   37888                           // half[2][256][72]   73728
#define SMEM_SZ 111616
#define ABUF(i) (O_ASH + (i) * 128 * APAD * 2)
#define BBUF(i) (O_BSH + (i) * 256 * APAD * 2)

__global__ __launch_bounds__(256, 1)
void main_mma_kernel(const float* __restrict__ b2, float* __restrict__ out)
{
    extern __shared__ __align__(16) char smem[];
    float* bias_s = (float*)(smem + O_BIAS);
    const uint32_t sb = smem_u32(smem);

    const int tid  = threadIdx.x;
    const int wid  = tid >> 5;
    const int lane = tid & 31;

    const int b  = blockIdx.z;
    const int t0 = (blockIdx.y >> 3) * 16;
    const int u0 = (blockIdx.y & 7) * 8;
    const int v0 = blockIdx.x * 256;

    const int warp_m = wid >> 2;          // 0..1 : rows warp_m*64
    const int warp_n = wid & 3;           // 0..3 : cols warp_n*64

    const float* eb = g_encp + (b * T_ + t0) * INNER_;
    const float* db = g_decp + (b * U_ + u0) * INNER_;

    bias_s[tid] = b2[v0 + tid];

    // per-thread cp.async source/dst for the B tile: 8 x 16B per chunk
    const int bv   = tid >> 3;            // 0..31 base row group (x8 iters)
    const int bseg = tid & 7;             // 0..7 : 16B segment
    const __half* w2p = g_w2f + (size_t)(v0 + bv) * INNER_ + bseg * 8;

    // tanh-stage coords
    const int hr  = tid >> 1;             // 0..127
    const int kh  = (tid & 1) * 32;
    const int tt  = hr >> 3, uu = hr & 7;
    const float* ep = eb + tt * INNER_ + kh;
    const float* dp = db + uu * INNER_ + kh;

    float acc[4][8][4] = {};              // [mtile16][ntile8][4]

    const int g   = lane >> 2;            // 0..7
    const int lq  = lane & 3;             // 0..3
    const int klo = lq * 2;

    // ---- preload B chunk 0 ----
    {
        #pragma unroll
        for (int it = 0; it < 8; it++)
            cp_async16(sb + BBUF(0) + ((it * 32 + bv) * APAD + bseg * 8) * 2,
                       w2p + (size_t)(it * 32) * INNER_);
        cp_commit();
    }

    for (int c = 0; c < 8; c++) {
        const int buf = c & 1;
        __half* AshB = (__half*)(smem + ABUF(buf));

        // ---- build h tile for chunk c: tanh(enc+dec) -> fp16 (global reads) ----
        {
            float4 ev[8], dv[8];
            #pragma unroll
            for (int i = 0; i < 8; i++) ev[i] = *(const float4*)(ep + c * 64 + i * 4);
            #pragma unroll
            for (int i = 0; i < 8; i++) dv[i] = *(const float4*)(dp + c * 64 + i * 4);
            #pragma unroll
            for (int i = 0; i < 8; i++) {
                float h0 = tanh_approx(ev[i].x + dv[i].x);
                float h1 = tanh_approx(ev[i].y + dv[i].y);
                float h2 = tanh_approx(ev[i].z + dv[i].z);
                float h3 = tanh_approx(ev[i].w + dv[i].w);
                __half2 p0 = __floats2half2_rn(h0, h1);
                __half2 p1 = __floats2half2_rn(h2, h3);
                uint2 pk;
                pk.x = *reinterpret_cast<uint32_t*>(&p0);
                pk.y = *reinterpret_cast<uint32_t*>(&p1);
                *(uint2*)&AshB[hr * APAD + kh + i * 4] = pk;
            }
        }

        cp_wait0();            // B chunk c landed
        __syncthreads();       // Ash+Bsh[buf] visible to all; MMA(c-1) done by all

        // ---- kick off B chunk c+1 into the other buffer (overlaps MMA) ----
        if (c < 7) {
            #pragma unroll
            for (int it = 0; it < 8; it++)
                cp_async16(sb + BBUF(buf ^ 1) + ((it * 32 + bv) * APAD + bseg * 8) * 2,
                           w2p + (size_t)(c + 1) * 64 + (size_t)(it * 32) * INNER_);
            cp_commit();
        }

        // ---- MMA: 4 k-steps of 16, warp tile 64x64 ----
        const __half* Ash = (const __half*)(smem + ABUF(buf));
        const __half* Bsh = (const __half*)(smem + BBUF(buf));
        #pragma unroll
        for (int ks = 0; ks < 4; ks++) {
            const int kb = ks * 16;
            uint32_t af[4][4];
            #pragma unroll
            for (int mt = 0; mt < 4; mt++) {
                const int rb = warp_m * 64 + mt * 16;
                af[mt][0] = *(const uint32_t*)&Ash[(rb + g    ) * APAD + kb + klo    ];
                af[mt][1] = *(const uint32_t*)&Ash[(rb + g + 8) * APAD + kb + klo    ];
                af[mt][2] = *(const uint32_t*)&Ash[(rb + g    ) * APAD + kb + klo + 8];
                af[mt][3] = *(const uint32_t*)&Ash[(rb + g + 8) * APAD + kb + klo + 8];
            }
            #pragma unroll
            for (int nt = 0; nt < 8; nt++) {
                const int nb = warp_n * 64 + nt * 8;
                uint32_t bf0 = *(const uint32_t*)&Bsh[(nb + g) * APAD + kb + klo    ];
                uint32_t bf1 = *(const uint32_t*)&Bsh[(nb + g) * APAD + kb + klo + 8];
                #pragma unroll
                for (int mt = 0; mt < 4; mt++) {
                    asm volatile(
                        "mma.sync.aligned.m16n8k16.row.col.f32.f16.f16.f32 "
                        "{%0,%1,%2,%3}, {%4,%5,%6,%7}, {%8,%9}, {%0,%1,%2,%3};"
                        : "+f"(acc[mt][nt][0]), "+f"(acc[mt][nt][1]),
                          "+f"(acc[mt][nt][2]), "+f"(acc[mt][nt][3])
                        : "r"(af[mt][0]), "r"(af[mt][1]), "r"(af[mt][2]), "r"(af[mt][3]),
                          "r"(bf0), "r"(bf1));
                }
            }
        }
    }

    // ---- epilogue: +bias, store fp32 (acc is register-private; no sync) ----
    #pragma unroll
    for (int mt = 0; mt < 4; mt++) {
        const int rb = warp_m * 64 + mt * 16;
        #pragma unroll
        for (int half = 0; half < 2; half++) {
            const int r   = rb + g + half * 8;
            const int tt2 = r >> 3, uu2 = r & 7;
            float* op = out + ((size_t)((b * T_ + t0 + tt2) * U_ + u0 + uu2)) * VOCAB_ + v0;
            #pragma unroll
            for (int nt = 0; nt < 8; nt++) {
                const int col = warp_n * 64 + nt * 8 + klo;
                float2 s;
                s.x = acc[mt][nt][half * 2 + 0] + bias_s[col + 0];
                s.y = acc[mt][nt][half * 2 + 1] + bias_s[col + 1];
                *(float2*)(op + col) = s;
            }
        }
    }
}

// ---------------------------------------------------------------------------
extern "C" void kernel_launch(void* const* d_in, const int* in_sizes, int n_in,
                              void* d_out, int out_size)
{
    const float* enc = (const float*)d_in[0];   // (4,400,320)
    const float* dec = (const float*)d_in[1];   // (4,64,320)
    const float* W1  = (const float*)d_in[2];   // (512,640)
    const float* b1  = (const float*)d_in[3];   // (512,)
    const float* W2  = (const float*)d_in[4];   // (1024,512)
    const float* b2  = (const float*)d_in[5];   // (1024,)
    float* out = (float*)d_out;                 // (4,400,64,1024) f32

    proj_kernel<<<dim3(25, 8), 256>>>(enc, W1, b1, 0);
    proj_kernel<<<dim3(4, 8),  256>>>(dec, W1, b1, 1);
    w2half_kernel<<<(VOCAB_ * INNER_ + 255) / 256, 256>>>(W2);

    static int smem_set = 0;
    if (!smem_set) {
        cudaFuncSetAttribute(main_mma_kernel,
                             cudaFuncAttributeMaxDynamicSharedMemorySize, SMEM_SZ);
        smem_set = 1;
    }
    main_mma_kernel<<<dim3(4, 200, 4), 256, SMEM_SZ>>>(b2, out);
}

// round 10
// speedup vs baseline: 1.0007x; 1.0007x over previous
#include <cuda_runtime.h>
#include <cuda_fp16.h>
#include <cstdint>

#define B_     4
#define T_     400
#define U_     64
#define E_     320
#define INNER_ 512
#define VOCAB_ 1024

// ---------------------------------------------------------------------------
// Device-global scratch (no runtime allocation allowed)
// ---------------------------------------------------------------------------
__device__ float  g_encp[B_ * T_ * INNER_];   // enc @ W1[:, :E]
__device__ float  g_decp[B_ * U_ * INNER_];   // dec @ W1[:, E:] + b1
__device__ __half g_w2f[VOCAB_ * INNER_];     // W2 in fp16 (rn)

__device__ __forceinline__ float tanh_approx(float x) {
    float y; asm("tanh.approx.f32 %0, %1;" : "=f"(y) : "f"(x)); return y;
}
__device__ __forceinline__ uint32_t smem_u32(const void* p) {
    uint32_t a;
    asm("{ .reg .u64 t; cvta.to.shared.u64 t, %1; cvt.u32.u64 %0, t; }" : "=r"(a) : "l"(p));
    return a;
}
__device__ __forceinline__ void cp_async16(uint32_t dst, const void* src) {
    asm volatile("cp.async.ca.shared.global [%0], [%1], 16;" :: "r"(dst), "l"(src));
}
__device__ __forceinline__ void cp_commit() {
    asm volatile("cp.async.commit_group;" ::: "memory");
}
__device__ __forceinline__ void cp_wait0() {
    asm volatile("cp.async.wait_group 0;" ::: "memory");
}

// ---------------------------------------------------------------------------
// Kernel 1: projection GEMM (unchanged, passing)
// ---------------------------------------------------------------------------
__global__ __launch_bounds__(256)
void proj_kernel(const float* __restrict__ A, const float* __restrict__ W1,
                 const float* __restrict__ b1, int isDec)
{
    __shared__ float As[16][64];
    __shared__ float Ws[16][68];

    const int tid  = threadIdx.x;
    const int m0   = blockIdx.x * 64;
    const int n0   = blockIdx.y * 64;
    const int koff = isDec ? E_ : 0;

    float acc[4][4] = {};

    for (int k0 = 0; k0 < E_; k0 += 16) {
        #pragma unroll
        for (int i = tid; i < 64 * 16; i += 256) {
            int r = i >> 4, k = i & 15;
            As[k][r] = A[(m0 + r) * E_ + k0 + k];
        }
        #pragma unroll
        for (int i = tid; i < 64 * 16; i += 256) {
            int c = i >> 4, k = i & 15;
            Ws[k][c] = W1[(n0 + c) * (2 * E_) + koff + k0 + k];
        }
        __syncthreads();

        const int ty = tid >> 4, tx = tid & 15;
        #pragma unroll
        for (int k = 0; k < 16; k++) {
            float a[4], w[4];
            #pragma unroll
            for (int i = 0; i < 4; i++) a[i] = As[k][ty * 4 + i];
            #pragma unroll
            for (int j = 0; j < 4; j++) w[j] = Ws[k][tx * 4 + j];
            #pragma unroll
            for (int i = 0; i < 4; i++)
                #pragma unroll
                for (int j = 0; j < 4; j++)
                    acc[i][j] = fmaf(a[i], w[j], acc[i][j]);
        }
        __syncthreads();
    }

    const int ty = tid >> 4, tx = tid & 15;
    float* C = isDec ? g_decp : g_encp;
    #pragma unroll
    for (int i = 0; i < 4; i++)
        #pragma unroll
        for (int j = 0; j < 4; j++) {
            float v = acc[i][j];
            if (isDec) v += b1[n0 + tx * 4 + j];
            C[(m0 + ty * 4 + i) * INNER_ + n0 + tx * 4 + j] = v;
        }
}

// ---------------------------------------------------------------------------
// Kernel 2: W2 fp32 -> fp16 (one-time)
// ---------------------------------------------------------------------------
__global__ __launch_bounds__(256)
void w2half_kernel(const float* __restrict__ W2)
{
    int i = blockIdx.x * 256 + threadIdx.x;
    if (i < VOCAB_ * INNER_) g_w2f[i] = __float2half_rn(W2[i]);
}

// ---------------------------------------------------------------------------
// Kernel 3: fused mma.sync kernel. R7 phase structure + full cp.async
// double-buffered prefetch of es/ds/B (prefetch c+1 lands during tanh+MMA c).
//   Block tile: 128 rows (16t x 8u) x 256 vocab, K-chunks of 64 (8 chunks).
//   8 warps 2(m) x 4(n), warp tile 64x64 via m16n8k16 fp16->f32.
//   Ash single-buffered (safe: tanh(c+1) writes only after sync1(c+1), which
//   every warp reaches only after its MMA(c) reads are done).
// ---------------------------------------------------------------------------
#define APAD 72

// dynamic smem layout (bytes)
#define O_BIAS  0                                // float[256]         1024
#define O_ES    1024                             // float[2][16][64]   8192
#define O_DS    9216                             // float[2][8][64]    4096
#define O_ASH   13312                            // half[128][72]     18432
#define O_BSH   31744                            // half[2][256][72]  73728
#define SMEM_SZ 105472
#define ESB(i) (O_ES + (i) * 4096)
#define DSB(i) (O_DS + (i) * 2048)
#define BBUF(i) (O_BSH + (i) * 256 * APAD * 2)

__global__ __launch_bounds__(256, 1)
void main_mma_kernel(const float* __restrict__ b2, float* __restrict__ out)
{
    extern __shared__ __align__(16) char smem[];
    float* bias_s = (float*)(smem + O_BIAS);
    const uint32_t sb = smem_u32(smem);

    const int tid  = threadIdx.x;
    const int wid  = tid >> 5;
    const int lane = tid & 31;

    const int b  = blockIdx.z;
    const int t0 = (blockIdx.y >> 3) * 16;
    const int u0 = (blockIdx.y & 7) * 8;
    const int v0 = blockIdx.x * 256;

    const int warp_m = wid >> 2;          // 0..1 : rows warp_m*64
    const int warp_n = wid & 3;           // 0..3 : cols warp_n*64

    const float* eb = g_encp + (b * T_ + t0) * INNER_;
    const float* db = g_decp + (b * U_ + u0) * INNER_;

    bias_s[tid] = b2[v0 + tid];

    // cp.async coordinates
    const int er  = tid >> 4, eseg = tid & 15;          // es: 16 rows x 16 segs
    const int bv  = tid >> 3, bseg = tid & 7;           // B : 32-row groups x 8 segs
    const __half* w2p = g_w2f + (size_t)(v0 + bv) * INNER_ + bseg * 8;
    const float*  epg = eb + er * INNER_ + eseg * 4;
    const float*  dpg = db + (er & 7) * INNER_ + eseg * 4;   // only tid<128 uses

    // tanh-stage coords
    const int hr  = tid >> 1;             // 0..127
    const int kh  = (tid & 1) * 32;
    const int tt  = hr >> 3, uu = hr & 7;

    float acc[4][8][4] = {};              // [mtile16][ntile8][4]

    const int g   = lane >> 2;            // 0..7
    const int lq  = lane & 3;             // 0..3
    const int klo = lq * 2;

    // ---- prefetch helper (chunk cc into buffer bb) ----
    #define PREFETCH(cc, bb)                                                        \
    {                                                                               \
        cp_async16(sb + ESB(bb) + (er * 64 + eseg * 4) * 4, epg + (cc) * 64);       \
        if (tid < 128)                                                              \
            cp_async16(sb + DSB(bb) + ((er & 7) * 64 + eseg * 4) * 4,               \
                       dpg + (cc) * 64);                                            \
        _Pragma("unroll")                                                           \
        for (int it = 0; it < 8; it++)                                              \
            cp_async16(sb + BBUF(bb) + ((it * 32 + bv) * APAD + bseg * 8) * 2,      \
                       w2p + (size_t)(cc) * 64 + (size_t)(it * 32) * INNER_);       \
        cp_commit();                                                                \
    }

    PREFETCH(0, 0);

    for (int c = 0; c < 8; c++) {
        const int buf = c & 1;

        cp_wait0();            // chunk c's es/ds/B landed (this thread's part)
        __syncthreads();       // all threads' parts visible; MMA(c-1) done by all

        // ---- kick off prefetch of chunk c+1 (overlaps tanh + MMA) ----
        if (c < 7) PREFETCH(c + 1, buf ^ 1);

        // ---- build h tile: tanh(enc+dec) -> fp16 (SMEM reads, broadcast) ----
        {
            const float* esp = (const float*)(smem + ESB(buf)) + tt * 64 + kh;
            const float* dsp = (const float*)(smem + DSB(buf)) + uu * 64 + kh;
            __half* AshB = (__half*)(smem + O_ASH);
            #pragma unroll
            for (int i = 0; i < 8; i++) {
                float4 ev = *(const float4*)(esp + i * 4);
                float4 dv = *(const float4*)(dsp + i * 4);
                float h0 = tanh_approx(ev.x + dv.x);
                float h1 = tanh_approx(ev.y + dv.y);
                float h2 = tanh_approx(ev.z + dv.z);
                float h3 = tanh_approx(ev.w + dv.w);
                __half2 p0 = __floats2half2_rn(h0, h1);
                __half2 p1 = __floats2half2_rn(h2, h3);
                uint2 pk;
                pk.x = *reinterpret_cast<uint32_t*>(&p0);
                pk.y = *reinterpret_cast<uint32_t*>(&p1);
                *(uint2*)&AshB[hr * APAD + kh + i * 4] = pk;
            }
        }
        __syncthreads();       // Ash ready for all warps

        // ---- MMA: 4 k-steps of 16, warp tile 64x64 ----
        const __half* Ash = (const __half*)(smem + O_ASH);
        const __half* Bsh = (const __half*)(smem + BBUF(buf));
        #pragma unroll
        for (int ks = 0; ks < 4; ks++) {
            const int kb = ks * 16;
            uint32_t af[4][4];
            #pragma unroll
            for (int mt = 0; mt < 4; mt++) {
                const int rb = warp_m * 64 + mt * 16;
                af[mt][0] = *(const uint32_t*)&Ash[(rb + g    ) * APAD + kb + klo    ];
                af[mt][1] = *(const uint32_t*)&Ash[(rb + g + 8) * APAD + kb + klo    ];
                af[mt][2] = *(const uint32_t*)&Ash[(rb + g    ) * APAD + kb + klo + 8];
                af[mt][3] = *(const uint32_t*)&Ash[(rb + g + 8) * APAD + kb + klo + 8];
            }
            #pragma unroll
            for (int nt = 0; nt < 8; nt++) {
                const int nb = warp_n * 64 + nt * 8;
                uint32_t bf0 = *(const uint32_t*)&Bsh[(nb + g) * APAD + kb + klo    ];
                uint32_t bf1 = *(const uint32_t*)&Bsh[(nb + g) * APAD + kb + klo + 8];
                #pragma unroll
                for (int mt = 0; mt < 4; mt++) {
                    asm volatile(
                        "mma.sync.aligned.m16n8k16.row.col.f32.f16.f16.f32 "
                        "{%0,%1,%2,%3}, {%4,%5,%6,%7}, {%8,%9}, {%0,%1,%2,%3};"
                        : "+f"(acc[mt][nt][0]), "+f"(acc[mt][nt][1]),
                          "+f"(acc[mt][nt][2]), "+f"(acc[mt][nt][3])
                        : "r"(af[mt][0]), "r"(af[mt][1]), "r"(af[mt][2]), "r"(af[mt][3]),
                          "r"(bf0), "r"(bf1));
                }
            }
        }
    }

    // ---- epilogue: +bias, store fp32 (acc register-private; no sync) ----
    #pragma unroll
    for (int mt = 0; mt < 4; mt++) {
        const int rb = warp_m * 64 + mt * 16;
        #pragma unroll
        for (int half = 0; half < 2; half++) {
            const int r   = rb + g + half * 8;
            const int tt2 = r >> 3, uu2 = r & 7;
            float* op = out + ((size_t)((b * T_ + t0 + tt2) * U_ + u0 + uu2)) * VOCAB_ + v0;
            #pragma unroll
            for (int nt = 0; nt < 8; nt++) {
                const int col = warp_n * 64 + nt * 8 + klo;
                float2 s;
                s.x = acc[mt][nt][half * 2 + 0] + bias_s[col + 0];
                s.y = acc[mt][nt][half * 2 + 1] + bias_s[col + 1];
                *(float2*)(op + col) = s;
            }
        }
    }
}

// ---------------------------------------------------------------------------
extern "C" void kernel_launch(void* const* d_in, const int* in_sizes, int n_in,
                              void* d_out, int out_size)
{
    const float* enc = (const float*)d_in[0];   // (4,400,320)
    const float* dec = (const float*)d_in[1];   // (4,64,320)
    const float* W1  = (const float*)d_in[2];   // (512,640)
    const float* b1  = (const float*)d_in[3];   // (512,)
    const float* W2  = (const float*)d_in[4];   // (1024,512)
    const float* b2  = (const float*)d_in[5];   // (1024,)
    float* out = (float*)d_out;                 // (4,400,64,1024) f32

    proj_kernel<<<dim3(25, 8), 256>>>(enc, W1, b1, 0);
    proj_kernel<<<dim3(4, 8),  256>>>(dec, W1, b1, 1);
    w2half_kernel<<<(VOCAB_ * INNER_ + 255) / 256, 256>>>(W2);

    static int smem_set = 0;
    if (!smem_set) {
        cudaFuncSetAttribute(main_mma_kernel,
                             cudaFuncAttributeMaxDynamicSharedMemorySize, SMEM_SZ);
        smem_set = 1;
    }
    main_mma_kernel<<<dim3(4, 200, 4), 256, SMEM_SZ>>>(b2, out);
}